// round 6
// baseline (speedup 1.0000x reference)
#include <cuda_runtime.h>
#include <cuda_bf16.h>
#include <cstdint>

// Problem dims (fixed by setup_inputs)
#define SLEN 1024
#define BSZ  32
#define INDIM 512
#define NH   8
#define HD   64
#define NTOK (SLEN*BSZ)          // 32768
#define NPROJ (NH*(3*HD+1))      // 1544
#define LN_EPS 1e-5f

// ---------------- scratch (device globals; no runtime alloc) ----------------
__device__ __align__(256) float g_qkvb[NTOK * NPROJ];            // projection output (fp32)
__device__ __align__(256) unsigned short g_hhi[NTOK * INDIM];    // LN output split
__device__ __align__(256) unsigned short g_hlo[NTOK * INDIM];
__device__ __align__(256) unsigned short g_ohi[NTOK * INDIM];    // recurrence out split
__device__ __align__(256) unsigned short g_olo[NTOK * INDIM];
__device__ __align__(256) unsigned short g_wshi[INDIM * NPROJ];  // w_slow split
__device__ __align__(256) unsigned short g_wslo[INDIM * NPROJ];
__device__ __align__(256) unsigned short g_wohi[INDIM * INDIM];  // w_out split
__device__ __align__(256) unsigned short g_wolo[INDIM * INDIM];

// ---------------- small helpers ----------------
__device__ __forceinline__ unsigned smem_u32(const void* p) {
    return (unsigned)__cvta_generic_to_shared(p);
}
__device__ __forceinline__ void cp16(unsigned dst, const void* src, int sz) {
    asm volatile("cp.async.cg.shared.global [%0], [%1], 16, %2;\n"
                 :: "r"(dst), "l"(src), "r"(sz));
}
__device__ __forceinline__ void cp4(unsigned dst, const void* src) {
    asm volatile("cp.async.ca.shared.global [%0], [%1], 4;\n"
                 :: "r"(dst), "l"(src));
}
__device__ __forceinline__ void cp_commit() {
    asm volatile("cp.async.commit_group;\n" ::: "memory");
}
__device__ __forceinline__ void ldm_x4(unsigned& r0, unsigned& r1, unsigned& r2, unsigned& r3, unsigned addr) {
    asm volatile("ldmatrix.sync.aligned.m8n8.x4.shared.b16 {%0,%1,%2,%3}, [%4];"
                 : "=r"(r0), "=r"(r1), "=r"(r2), "=r"(r3) : "r"(addr));
}
__device__ __forceinline__ void ldm_x4_t(unsigned& r0, unsigned& r1, unsigned& r2, unsigned& r3, unsigned addr) {
    asm volatile("ldmatrix.sync.aligned.m8n8.x4.trans.shared.b16 {%0,%1,%2,%3}, [%4];"
                 : "=r"(r0), "=r"(r1), "=r"(r2), "=r"(r3) : "r"(addr));
}
__device__ __forceinline__ void mma16816(float* d, const unsigned* a, unsigned b0, unsigned b1) {
    asm volatile("mma.sync.aligned.m16n8k16.row.col.f32.bf16.bf16.f32 "
                 "{%0,%1,%2,%3}, {%4,%5,%6,%7}, {%8,%9}, {%0,%1,%2,%3};"
                 : "+f"(d[0]), "+f"(d[1]), "+f"(d[2]), "+f"(d[3])
                 : "r"(a[0]), "r"(a[1]), "r"(a[2]), "r"(a[3]), "r"(b0), "r"(b1));
}
__device__ __forceinline__ unsigned short bf16_bits(__nv_bfloat16 v) {
    return *reinterpret_cast<unsigned short*>(&v);
}

// ---------------- LayerNorm (emits bf16 hi/lo split) ----------------
__global__ __launch_bounds__(128) void ln_kernel(const float* __restrict__ x,
                                                 const float* __restrict__ gamma,
                                                 const float* __restrict__ beta,
                                                 unsigned short* __restrict__ hhi,
                                                 unsigned short* __restrict__ hlo) {
    int row = blockIdx.x;
    int tid = threadIdx.x;
    int lane = tid & 31, wid = tid >> 5;
    const float4* xr = (const float4*)(x + (size_t)row * INDIM);
    float4 v = xr[tid];

    float s = v.x + v.y + v.z + v.w;
    #pragma unroll
    for (int o = 16; o > 0; o >>= 1) s += __shfl_xor_sync(0xffffffffu, s, o);
    __shared__ float sm[4], sm2[4];
    if (lane == 0) sm[wid] = s;
    __syncthreads();
    float mu = (sm[0] + sm[1] + sm[2] + sm[3]) * (1.0f / INDIM);

    float dx = v.x - mu, dy = v.y - mu, dz = v.z - mu, dw = v.w - mu;
    float sq = dx*dx + dy*dy + dz*dz + dw*dw;
    #pragma unroll
    for (int o = 16; o > 0; o >>= 1) sq += __shfl_xor_sync(0xffffffffu, sq, o);
    if (lane == 0) sm2[wid] = sq;
    __syncthreads();
    float var = (sm2[0] + sm2[1] + sm2[2] + sm2[3]) * (1.0f / INDIM);
    float rstd = rsqrtf(var + LN_EPS);

    float4 g = ((const float4*)gamma)[tid];
    float4 b = ((const float4*)beta)[tid];
    float o0 = dx * rstd * g.x + b.x;
    float o1 = dy * rstd * g.y + b.y;
    float o2 = dz * rstd * g.z + b.z;
    float o3 = dw * rstd * g.w + b.w;

    __nv_bfloat16 h0 = __float2bfloat16(o0), h1 = __float2bfloat16(o1);
    __nv_bfloat16 h2 = __float2bfloat16(o2), h3 = __float2bfloat16(o3);
    __nv_bfloat16 l0 = __float2bfloat16(o0 - __bfloat162float(h0));
    __nv_bfloat16 l1 = __float2bfloat16(o1 - __bfloat162float(h1));
    __nv_bfloat16 l2 = __float2bfloat16(o2 - __bfloat162float(h2));
    __nv_bfloat16 l3 = __float2bfloat16(o3 - __bfloat162float(h3));

    ushort4 hv; hv.x = bf16_bits(h0); hv.y = bf16_bits(h1); hv.z = bf16_bits(h2); hv.w = bf16_bits(h3);
    ushort4 lv; lv.x = bf16_bits(l0); lv.y = bf16_bits(l1); lv.z = bf16_bits(l2); lv.w = bf16_bits(l3);
    *(ushort4*)(hhi + (size_t)row * INDIM + 4 * tid) = hv;
    *(ushort4*)(hlo + (size_t)row * INDIM + 4 * tid) = lv;
}

// ---------------- weight split ----------------
__global__ void split_kernel(const float* __restrict__ w,
                             unsigned short* __restrict__ hi,
                             unsigned short* __restrict__ lo, int n) {
    int i = blockIdx.x * 256 + threadIdx.x;
    if (i < n) {
        float f = w[i];
        __nv_bfloat16 h = __float2bfloat16(f);
        __nv_bfloat16 l = __float2bfloat16(f - __bfloat162float(h));
        hi[i] = bf16_bits(h);
        lo[i] = bf16_bits(l);
    }
}

// ---------------- split-bf16 tensor-core GEMM (3-stage pipeline) ----------------
#define STG   20992
#define A_LO  6144
#define B_HI  12288
#define B_P   4352
#define SMEM_GEMM (3 * STG)

__global__ __launch_bounds__(256) void gemm_split(const __nv_bfloat16* __restrict__ Ahi,
                                                  const __nv_bfloat16* __restrict__ Alo,
                                                  const __nv_bfloat16* __restrict__ Bhi,
                                                  const __nv_bfloat16* __restrict__ Blo,
                                                  const float* __restrict__ RES,
                                                  float* __restrict__ C,
                                                  int M, int N, int K) {
    extern __shared__ __align__(128) char dsm[];

    const int tid = threadIdx.x, lane = tid & 31, wid = tid >> 5;
    const int m_blk = blockIdx.y * 128, n_blk = blockIdx.x * 128;
    const int wm = (wid & 3) * 32, wn = (wid >> 2) * 64;

    const int ar = tid >> 1, aseg = (tid & 1) * 8;
    const int bk = tid >> 4, bseg = (tid & 15) * 8;
    const __nv_bfloat16* agh = Ahi + (size_t)(m_blk + ar) * K + aseg;
    const __nv_bfloat16* agl = Alo + (size_t)(m_blk + ar) * K + aseg;
    const __nv_bfloat16* bgh = Bhi + (size_t)bk * N + n_blk + bseg;
    const __nv_bfloat16* bgl = Blo + (size_t)bk * N + n_blk + bseg;
    const int bsz = (n_blk + bseg + 8 <= N) ? 16 : 0;

    const unsigned sb = smem_u32(dsm);
    const unsigned adst = sb + (ar * 24 + aseg) * 2;
    const unsigned bdst = sb + B_HI + (bk * 136 + bseg) * 2;

#define GISSUE(T, ST) do { \
    unsigned off_ = (unsigned)(ST) * STG; \
    cp16(adst + off_,         agh + (T) * 16, 16); \
    cp16(adst + off_ + A_LO,  agl + (T) * 16, 16); \
    cp16(bdst + off_,         bgh + (size_t)(T) * 16 * N, bsz); \
    cp16(bdst + off_ + B_P,   bgl + (size_t)(T) * 16 * N, bsz); \
    cp_commit(); } while (0)

    const int arow = lane & 15;
    const unsigned aLd = sb + ((wm + arow) * 24 + ((lane >> 4) * 8)) * 2;
    const unsigned bLd = sb + B_HI + ((lane & 15) * 136 + wn + ((lane >> 4) * 8)) * 2;

    float acc[2][8][4];
    #pragma unroll
    for (int i = 0; i < 2; i++)
        #pragma unroll
        for (int j = 0; j < 8; j++)
            #pragma unroll
            for (int q = 0; q < 4; q++) acc[i][j][q] = 0.0f;

    const int NT = K / 16;
    GISSUE(0, 0);
    GISSUE(1, 1);

    int st = 0, st2 = 2;
    for (int t = 0; t < NT; t++) {
        if (t < NT - 1) asm volatile("cp.async.wait_group 1;\n" ::: "memory");
        else            asm volatile("cp.async.wait_group 0;\n" ::: "memory");
        __syncthreads();

        if (t + 2 < NT) GISSUE(t + 2, st2);

        const unsigned aOf = aLd + st * STG;
        const unsigned bOf = bLd + st * STG;

        unsigned ahi[2][4], bhi[4][4], tmp[4];
        #pragma unroll
        for (int mf = 0; mf < 2; mf++)
            ldm_x4(ahi[mf][0], ahi[mf][1], ahi[mf][2], ahi[mf][3], aOf + mf * 768);
        #pragma unroll
        for (int g = 0; g < 4; g++)
            ldm_x4_t(bhi[g][0], bhi[g][1], bhi[g][2], bhi[g][3], bOf + g * 32);

        #pragma unroll
        for (int mf = 0; mf < 2; mf++)
            #pragma unroll
            for (int nf = 0; nf < 8; nf++)
                mma16816(acc[mf][nf], ahi[mf], bhi[nf >> 1][(nf & 1) * 2], bhi[nf >> 1][(nf & 1) * 2 + 1]);
        #pragma unroll
        for (int mf = 0; mf < 2; mf++) {
            ldm_x4(tmp[0], tmp[1], tmp[2], tmp[3], aOf + A_LO + mf * 768);
            #pragma unroll
            for (int nf = 0; nf < 8; nf++)
                mma16816(acc[mf][nf], tmp, bhi[nf >> 1][(nf & 1) * 2], bhi[nf >> 1][(nf & 1) * 2 + 1]);
        }
        #pragma unroll
        for (int g = 0; g < 4; g++) {
            ldm_x4_t(tmp[0], tmp[1], tmp[2], tmp[3], bOf + B_P + g * 32);
            #pragma unroll
            for (int mf = 0; mf < 2; mf++) {
                mma16816(acc[mf][2 * g],     ahi[mf], tmp[0], tmp[1]);
                mma16816(acc[mf][2 * g + 1], ahi[mf], tmp[2], tmp[3]);
            }
        }

        st = (st == 2) ? 0 : st + 1;
        st2 = (st2 == 2) ? 0 : st2 + 1;
    }

    #pragma unroll
    for (int mf = 0; mf < 2; mf++) {
        int row = m_blk + wm + mf * 16 + (lane >> 2);
        #pragma unroll
        for (int nf = 0; nf < 8; nf++) {
            int col = n_blk + wn + nf * 8 + (lane & 3) * 2;
            if (col < N) {
                float2 v0 = make_float2(acc[mf][nf][0], acc[mf][nf][1]);
                float2 v1 = make_float2(acc[mf][nf][2], acc[mf][nf][3]);
                if (RES) {
                    float2 r0 = *(const float2*)(RES + (size_t)row * N + col);
                    float2 r1 = *(const float2*)(RES + (size_t)(row + 8) * N + col);
                    v0.x += r0.x; v0.y += r0.y; v1.x += r1.x; v1.y += r1.y;
                }
                *(float2*)(C + (size_t)row * N + col) = v0;
                *(float2*)(C + (size_t)(row + 8) * N + col) = v1;
            }
        }
    }
#undef GISSUE
}

// ---------------- Delta-rule recurrence (cp.async ring staged) ----------------
// 2 heads/CTA (grid 128, single wave), 256 threads per head (8 warps).
// Thread (w8, lane): r = w8*8 + (lane&7), seg = lane>>3; owns W[r][seg*16..+16).
// qkvb staged through an 8-slot smem ring via per-thread 4B cp.async, issued
// 6 steps ahead (covers DRAM latency). elu producer runs one step ahead into a
// 4-deep sq/sk buffer. One __syncthreads + one wait_group per step.
__global__ __launch_bounds__(512) void delta_kernel(const float* __restrict__ qkvb,
                                                    unsigned short* __restrict__ ohi,
                                                    unsigned short* __restrict__ olo) {
    const int tid = threadIdx.x;
    const int hl = tid >> 8;             // head within CTA (0/1)
    const int ht = tid & 255;
    const int lane = tid & 31;
    const int w8 = ht >> 5;              // warp within head (0..7)
    const int r = w8 * 8 + (lane & 7);   // W row (0..63)
    const int seg = lane >> 3;           // column segment (0..3)
    const int j0 = seg * 16;
    const int bh = blockIdx.x * 2 + hl;  // 0..255
    const int b = bh >> 3, h = bh & 7;

    __shared__ float ring[2][8][200];    // [head][slot][193 floats used]
    __shared__ float sq[2][4][64];       // [head][t mod 4][dim]
    __shared__ float sk[2][4][64];

    const float* base = qkvb + (size_t)b * NPROJ + h * 193;
    const size_t tstr = (size_t)BSZ * NPROJ;

    float W[16];
    #pragma unroll
    for (int i = 0; i < 16; i++) W[i] = 0.0f;

    // prologue: issue steps 0..5 into slots 0..5 (one commit group per step)
    if (ht < 193) {
        #pragma unroll
        for (int s = 0; s < 6; s++) {
            cp4(smem_u32(&ring[hl][s][ht]), base + (size_t)s * tstr + ht);
            cp_commit();
        }
        asm volatile("cp.async.wait_group 4;\n" ::: "memory");   // steps 0,1 complete
    }
    __syncthreads();

    // elu for step 0
    if (ht < 128) {
        float xv = ring[hl][0][ht];
        float y = (xv > 0.f) ? (xv + 1.0f) : __expf(xv);
        if (ht < 64) sq[hl][0][ht] = y;
        else         sk[hl][0][ht - 64] = y;
    }
    __syncthreads();

    for (int t = 0; t < SLEN; t++) {
        const int tb = t & 3;

        // phase 1: elu for step t+1 (ring slot (t+1)&7 guaranteed by prev wait+bar)
        if (ht < 128 && t + 1 < SLEN) {
            float xv = ring[hl][(t + 1) & 7][ht];
            float y = (xv > 0.f) ? (xv + 1.0f) : __expf(xv);
            if (ht < 64) sq[hl][(t + 1) & 3][ht] = y;
            else         sk[hl][(t + 1) & 3][ht - 64] = y;
        }

        // phase 2: issue step t+6 into slot (t+6)&7 (held step t-2, fully
        // consumed before the previous barrier); always commit to keep
        // per-thread group counting uniform.
        if (ht < 193) {
            if (t + 6 < SLEN)
                cp4(smem_u32(&ring[hl][(t + 6) & 7][ht]), base + (size_t)(t + 6) * tstr + ht);
            cp_commit();
            asm volatile("cp.async.wait_group 4;\n" ::: "memory");  // covers step t+2
        }
        __syncthreads();

        // phase 3: compute step t from smem only
        const float* rg = ring[hl][t & 7];
        float vt = rg[128 + r];
        float xb = rg[192];
        float bsig = 1.0f / (1.0f + __expf(-xb));

        float s1 = sq[hl][tb][lane] + sq[hl][tb][lane + 32];
        float s2 = sk[hl][tb][lane] + sk[hl][tb][lane + 32];
        #pragma unroll
        for (int o = 16; o > 0; o >>= 1) {
            s1 += __shfl_xor_sync(0xffffffffu, s1, o);
            s2 += __shfl_xor_sync(0xffffffffu, s2, o);
        }
        float rq = 1.0f / s1;
        float rk = 1.0f / s2;

        // partial dot W[r, j0:j0+16) . k
        float kreg[16];
        float pv0 = 0.f, pv1 = 0.f, pv2 = 0.f, pv3 = 0.f;
        #pragma unroll
        for (int j = 0; j < 4; j++) {
            float4 k4 = *(const float4*)&sk[hl][tb][j0 + j * 4];
            kreg[j*4+0] = k4.x; kreg[j*4+1] = k4.y; kreg[j*4+2] = k4.z; kreg[j*4+3] = k4.w;
            pv0 = fmaf(W[j*4+0], k4.x, pv0);
            pv1 = fmaf(W[j*4+1], k4.y, pv1);
            pv2 = fmaf(W[j*4+2], k4.z, pv2);
            pv3 = fmaf(W[j*4+3], k4.w, pv3);
        }
        float pv = (pv0 + pv1) + (pv2 + pv3);
        pv += __shfl_xor_sync(0xffffffffu, pv, 8);
        pv += __shfl_xor_sync(0xffffffffu, pv, 16);
        float upd = bsig * (vt - pv * rk) * rk;

        // W += upd*k ; po = W_new . q (partial)
        float po0 = 0.f, po1 = 0.f, po2 = 0.f, po3 = 0.f;
        #pragma unroll
        for (int j = 0; j < 4; j++) {
            float4 q4 = *(const float4*)&sq[hl][tb][j0 + j * 4];
            W[j*4+0] = fmaf(upd, kreg[j*4+0], W[j*4+0]);
            po0 = fmaf(W[j*4+0], q4.x, po0);
            W[j*4+1] = fmaf(upd, kreg[j*4+1], W[j*4+1]);
            po1 = fmaf(W[j*4+1], q4.y, po1);
            W[j*4+2] = fmaf(upd, kreg[j*4+2], W[j*4+2]);
            po2 = fmaf(W[j*4+2], q4.z, po2);
            W[j*4+3] = fmaf(upd, kreg[j*4+3], W[j*4+3]);
            po3 = fmaf(W[j*4+3], q4.w, po3);
        }
        float po = (po0 + po1) + (po2 + po3);
        po += __shfl_xor_sync(0xffffffffu, po, 8);
        po += __shfl_xor_sync(0xffffffffu, po, 16);
        float o = po * rq;

        if (seg == 0) {
            size_t oi = ((size_t)t * BSZ + b) * (size_t)INDIM + h * HD + r;
            __nv_bfloat16 oh = __float2bfloat16(o);
            __nv_bfloat16 ol = __float2bfloat16(o - __bfloat162float(oh));
            ohi[oi] = bf16_bits(oh);
            olo[oi] = bf16_bits(ol);
        }
    }
}

// ---------------- launch ----------------
extern "C" void kernel_launch(void* const* d_in, const int* in_sizes, int n_in,
                              void* d_out, int out_size) {
    const float* x      = (const float*)d_in[0];
    const float* gamma  = (const float*)d_in[1];
    const float* beta   = (const float*)d_in[2];
    const float* w_slow = (const float*)d_in[3];
    const float* w_out  = (const float*)d_in[4];
    float* out = (float*)d_out;

    float* qkvb;
    unsigned short *hhi, *hlo, *ohi, *olo, *wshi, *wslo, *wohi, *wolo;
    cudaGetSymbolAddress((void**)&qkvb, g_qkvb);
    cudaGetSymbolAddress((void**)&hhi, g_hhi);
    cudaGetSymbolAddress((void**)&hlo, g_hlo);
    cudaGetSymbolAddress((void**)&ohi, g_ohi);
    cudaGetSymbolAddress((void**)&olo, g_olo);
    cudaGetSymbolAddress((void**)&wshi, g_wshi);
    cudaGetSymbolAddress((void**)&wslo, g_wslo);
    cudaGetSymbolAddress((void**)&wohi, g_wohi);
    cudaGetSymbolAddress((void**)&wolo, g_wolo);

    // Idempotent, host-side, not stream-ordered: safe under graph capture.
    cudaFuncSetAttribute(gemm_split, cudaFuncAttributeMaxDynamicSharedMemorySize, SMEM_GEMM);

    ln_kernel<<<NTOK, 128>>>(x, gamma, beta, hhi, hlo);
    split_kernel<<<(INDIM * NPROJ + 255) / 256, 256>>>(w_slow, wshi, wslo, INDIM * NPROJ);
    split_kernel<<<(INDIM * INDIM + 255) / 256, 256>>>(w_out, wohi, wolo, INDIM * INDIM);

    dim3 g1((NPROJ + 127) / 128, NTOK / 128);
    gemm_split<<<g1, 256, SMEM_GEMM>>>((const __nv_bfloat16*)hhi, (const __nv_bfloat16*)hlo,
                                       (const __nv_bfloat16*)wshi, (const __nv_bfloat16*)wslo,
                                       nullptr, qkvb, NTOK, NPROJ, INDIM);

    delta_kernel<<<BSZ * NH / 2, 512>>>(qkvb, ohi, olo);

    dim3 g2(INDIM / 128, NTOK / 128);
    gemm_split<<<g2, 256, SMEM_GEMM>>>((const __nv_bfloat16*)ohi, (const __nv_bfloat16*)olo,
                                       (const __nv_bfloat16*)wohi, (const __nv_bfloat16*)wolo,
                                       x, out, NTOK, INDIM, NH * HD);
}

// round 7
// speedup vs baseline: 1.0001x; 1.0001x over previous
#include <cuda_runtime.h>
#include <cuda_bf16.h>
#include <cstdint>

// Problem dims (fixed by setup_inputs)
#define SLEN 1024
#define BSZ  32
#define INDIM 512
#define NH   8
#define HD   64
#define NTOK (SLEN*BSZ)          // 32768
#define NPROJ (NH*(3*HD+1))      // 1544
#define LN_EPS 1e-5f

// ---------------- scratch (device globals; no runtime alloc) ----------------
__device__ __align__(256) float g_qkvb[NTOK * NPROJ];            // projection output (fp32)
__device__ __align__(256) unsigned short g_hhi[NTOK * INDIM];    // LN output split
__device__ __align__(256) unsigned short g_hlo[NTOK * INDIM];
__device__ __align__(256) unsigned short g_ohi[NTOK * INDIM];    // recurrence out split
__device__ __align__(256) unsigned short g_olo[NTOK * INDIM];
__device__ __align__(256) unsigned short g_wshi[INDIM * NPROJ];  // w_slow split
__device__ __align__(256) unsigned short g_wslo[INDIM * NPROJ];
__device__ __align__(256) unsigned short g_wohi[INDIM * INDIM];  // w_out split
__device__ __align__(256) unsigned short g_wolo[INDIM * INDIM];

// ---------------- small helpers ----------------
__device__ __forceinline__ unsigned smem_u32(const void* p) {
    return (unsigned)__cvta_generic_to_shared(p);
}
__device__ __forceinline__ void cp16(unsigned dst, const void* src, int sz) {
    asm volatile("cp.async.cg.shared.global [%0], [%1], 16, %2;\n"
                 :: "r"(dst), "l"(src), "r"(sz));
}
__device__ __forceinline__ void cp4(unsigned dst, const void* src) {
    asm volatile("cp.async.ca.shared.global [%0], [%1], 4;\n"
                 :: "r"(dst), "l"(src));
}
__device__ __forceinline__ void cp_commit() {
    asm volatile("cp.async.commit_group;\n" ::: "memory");
}
__device__ __forceinline__ void ldm_x4(unsigned& r0, unsigned& r1, unsigned& r2, unsigned& r3, unsigned addr) {
    asm volatile("ldmatrix.sync.aligned.m8n8.x4.shared.b16 {%0,%1,%2,%3}, [%4];"
                 : "=r"(r0), "=r"(r1), "=r"(r2), "=r"(r3) : "r"(addr));
}
__device__ __forceinline__ void ldm_x4_t(unsigned& r0, unsigned& r1, unsigned& r2, unsigned& r3, unsigned addr) {
    asm volatile("ldmatrix.sync.aligned.m8n8.x4.trans.shared.b16 {%0,%1,%2,%3}, [%4];"
                 : "=r"(r0), "=r"(r1), "=r"(r2), "=r"(r3) : "r"(addr));
}
__device__ __forceinline__ void mma16816(float* d, const unsigned* a, unsigned b0, unsigned b1) {
    asm volatile("mma.sync.aligned.m16n8k16.row.col.f32.bf16.bf16.f32 "
                 "{%0,%1,%2,%3}, {%4,%5,%6,%7}, {%8,%9}, {%0,%1,%2,%3};"
                 : "+f"(d[0]), "+f"(d[1]), "+f"(d[2]), "+f"(d[3])
                 : "r"(a[0]), "r"(a[1]), "r"(a[2]), "r"(a[3]), "r"(b0), "r"(b1));
}
__device__ __forceinline__ unsigned short bf16_bits(__nv_bfloat16 v) {
    return *reinterpret_cast<unsigned short*>(&v);
}

// ---------------- LayerNorm (emits bf16 hi/lo split) ----------------
__global__ __launch_bounds__(128) void ln_kernel(const float* __restrict__ x,
                                                 const float* __restrict__ gamma,
                                                 const float* __restrict__ beta,
                                                 unsigned short* __restrict__ hhi,
                                                 unsigned short* __restrict__ hlo) {
    int row = blockIdx.x;
    int tid = threadIdx.x;
    int lane = tid & 31, wid = tid >> 5;
    const float4* xr = (const float4*)(x + (size_t)row * INDIM);
    float4 v = xr[tid];

    float s = v.x + v.y + v.z + v.w;
    #pragma unroll
    for (int o = 16; o > 0; o >>= 1) s += __shfl_xor_sync(0xffffffffu, s, o);
    __shared__ float sm[4], sm2[4];
    if (lane == 0) sm[wid] = s;
    __syncthreads();
    float mu = (sm[0] + sm[1] + sm[2] + sm[3]) * (1.0f / INDIM);

    float dx = v.x - mu, dy = v.y - mu, dz = v.z - mu, dw = v.w - mu;
    float sq = dx*dx + dy*dy + dz*dz + dw*dw;
    #pragma unroll
    for (int o = 16; o > 0; o >>= 1) sq += __shfl_xor_sync(0xffffffffu, sq, o);
    if (lane == 0) sm2[wid] = sq;
    __syncthreads();
    float var = (sm2[0] + sm2[1] + sm2[2] + sm2[3]) * (1.0f / INDIM);
    float rstd = rsqrtf(var + LN_EPS);

    float4 g = ((const float4*)gamma)[tid];
    float4 b = ((const float4*)beta)[tid];
    float o0 = dx * rstd * g.x + b.x;
    float o1 = dy * rstd * g.y + b.y;
    float o2 = dz * rstd * g.z + b.z;
    float o3 = dw * rstd * g.w + b.w;

    __nv_bfloat16 h0 = __float2bfloat16(o0), h1 = __float2bfloat16(o1);
    __nv_bfloat16 h2 = __float2bfloat16(o2), h3 = __float2bfloat16(o3);
    __nv_bfloat16 l0 = __float2bfloat16(o0 - __bfloat162float(h0));
    __nv_bfloat16 l1 = __float2bfloat16(o1 - __bfloat162float(h1));
    __nv_bfloat16 l2 = __float2bfloat16(o2 - __bfloat162float(h2));
    __nv_bfloat16 l3 = __float2bfloat16(o3 - __bfloat162float(h3));

    ushort4 hv; hv.x = bf16_bits(h0); hv.y = bf16_bits(h1); hv.z = bf16_bits(h2); hv.w = bf16_bits(h3);
    ushort4 lv; lv.x = bf16_bits(l0); lv.y = bf16_bits(l1); lv.z = bf16_bits(l2); lv.w = bf16_bits(l3);
    *(ushort4*)(hhi + (size_t)row * INDIM + 4 * tid) = hv;
    *(ushort4*)(hlo + (size_t)row * INDIM + 4 * tid) = lv;
}

// ---------------- weight split ----------------
__global__ void split_kernel(const float* __restrict__ w,
                             unsigned short* __restrict__ hi,
                             unsigned short* __restrict__ lo, int n) {
    int i = blockIdx.x * 256 + threadIdx.x;
    if (i < n) {
        float f = w[i];
        __nv_bfloat16 h = __float2bfloat16(f);
        __nv_bfloat16 l = __float2bfloat16(f - __bfloat162float(h));
        hi[i] = bf16_bits(h);
        lo[i] = bf16_bits(l);
    }
}

// ---------------- split-bf16 tensor-core GEMM (3-stage pipeline) ----------------
#define STG   20992
#define A_LO  6144
#define B_HI  12288
#define B_P   4352
#define SMEM_GEMM (3 * STG)

__global__ __launch_bounds__(256) void gemm_split(const __nv_bfloat16* __restrict__ Ahi,
                                                  const __nv_bfloat16* __restrict__ Alo,
                                                  const __nv_bfloat16* __restrict__ Bhi,
                                                  const __nv_bfloat16* __restrict__ Blo,
                                                  const float* __restrict__ RES,
                                                  float* __restrict__ C,
                                                  int M, int N, int K) {
    extern __shared__ __align__(128) char dsm[];

    const int tid = threadIdx.x, lane = tid & 31, wid = tid >> 5;
    const int m_blk = blockIdx.y * 128, n_blk = blockIdx.x * 128;
    const int wm = (wid & 3) * 32, wn = (wid >> 2) * 64;

    const int ar = tid >> 1, aseg = (tid & 1) * 8;
    const int bk = tid >> 4, bseg = (tid & 15) * 8;
    const __nv_bfloat16* agh = Ahi + (size_t)(m_blk + ar) * K + aseg;
    const __nv_bfloat16* agl = Alo + (size_t)(m_blk + ar) * K + aseg;
    const __nv_bfloat16* bgh = Bhi + (size_t)bk * N + n_blk + bseg;
    const __nv_bfloat16* bgl = Blo + (size_t)bk * N + n_blk + bseg;
    const int bsz = (n_blk + bseg + 8 <= N) ? 16 : 0;

    const unsigned sb = smem_u32(dsm);
    const unsigned adst = sb + (ar * 24 + aseg) * 2;
    const unsigned bdst = sb + B_HI + (bk * 136 + bseg) * 2;

#define GISSUE(T, ST) do { \
    unsigned off_ = (unsigned)(ST) * STG; \
    cp16(adst + off_,         agh + (T) * 16, 16); \
    cp16(adst + off_ + A_LO,  agl + (T) * 16, 16); \
    cp16(bdst + off_,         bgh + (size_t)(T) * 16 * N, bsz); \
    cp16(bdst + off_ + B_P,   bgl + (size_t)(T) * 16 * N, bsz); \
    cp_commit(); } while (0)

    const int arow = lane & 15;
    const unsigned aLd = sb + ((wm + arow) * 24 + ((lane >> 4) * 8)) * 2;
    const unsigned bLd = sb + B_HI + ((lane & 15) * 136 + wn + ((lane >> 4) * 8)) * 2;

    float acc[2][8][4];
    #pragma unroll
    for (int i = 0; i < 2; i++)
        #pragma unroll
        for (int j = 0; j < 8; j++)
            #pragma unroll
            for (int q = 0; q < 4; q++) acc[i][j][q] = 0.0f;

    const int NT = K / 16;
    GISSUE(0, 0);
    GISSUE(1, 1);

    int st = 0, st2 = 2;
    for (int t = 0; t < NT; t++) {
        if (t < NT - 1) asm volatile("cp.async.wait_group 1;\n" ::: "memory");
        else            asm volatile("cp.async.wait_group 0;\n" ::: "memory");
        __syncthreads();

        if (t + 2 < NT) GISSUE(t + 2, st2);

        const unsigned aOf = aLd + st * STG;
        const unsigned bOf = bLd + st * STG;

        unsigned ahi[2][4], bhi[4][4], tmp[4];
        #pragma unroll
        for (int mf = 0; mf < 2; mf++)
            ldm_x4(ahi[mf][0], ahi[mf][1], ahi[mf][2], ahi[mf][3], aOf + mf * 768);
        #pragma unroll
        for (int g = 0; g < 4; g++)
            ldm_x4_t(bhi[g][0], bhi[g][1], bhi[g][2], bhi[g][3], bOf + g * 32);

        #pragma unroll
        for (int mf = 0; mf < 2; mf++)
            #pragma unroll
            for (int nf = 0; nf < 8; nf++)
                mma16816(acc[mf][nf], ahi[mf], bhi[nf >> 1][(nf & 1) * 2], bhi[nf >> 1][(nf & 1) * 2 + 1]);
        #pragma unroll
        for (int mf = 0; mf < 2; mf++) {
            ldm_x4(tmp[0], tmp[1], tmp[2], tmp[3], aOf + A_LO + mf * 768);
            #pragma unroll
            for (int nf = 0; nf < 8; nf++)
                mma16816(acc[mf][nf], tmp, bhi[nf >> 1][(nf & 1) * 2], bhi[nf >> 1][(nf & 1) * 2 + 1]);
        }
        #pragma unroll
        for (int g = 0; g < 4; g++) {
            ldm_x4_t(tmp[0], tmp[1], tmp[2], tmp[3], bOf + B_P + g * 32);
            #pragma unroll
            for (int mf = 0; mf < 2; mf++) {
                mma16816(acc[mf][2 * g],     ahi[mf], tmp[0], tmp[1]);
                mma16816(acc[mf][2 * g + 1], ahi[mf], tmp[2], tmp[3]);
            }
        }

        st = (st == 2) ? 0 : st + 1;
        st2 = (st2 == 2) ? 0 : st2 + 1;
    }

    #pragma unroll
    for (int mf = 0; mf < 2; mf++) {
        int row = m_blk + wm + mf * 16 + (lane >> 2);
        #pragma unroll
        for (int nf = 0; nf < 8; nf++) {
            int col = n_blk + wn + nf * 8 + (lane & 3) * 2;
            if (col < N) {
                float2 v0 = make_float2(acc[mf][nf][0], acc[mf][nf][1]);
                float2 v1 = make_float2(acc[mf][nf][2], acc[mf][nf][3]);
                if (RES) {
                    float2 r0 = *(const float2*)(RES + (size_t)row * N + col);
                    float2 r1 = *(const float2*)(RES + (size_t)(row + 8) * N + col);
                    v0.x += r0.x; v0.y += r0.y; v1.x += r1.x; v1.y += r1.y;
                }
                *(float2*)(C + (size_t)row * N + col) = v0;
                *(float2*)(C + (size_t)(row + 8) * N + col) = v1;
            }
        }
    }
#undef GISSUE
}

// ---------------- Delta-rule recurrence (cp.async ring staged) ----------------
// 2 heads/CTA (grid 128, single wave), 256 threads per head (8 warps).
// Thread (w8, lane): r = w8*8 + (lane&7), seg = lane>>3; owns W[r][seg*16..+16).
// qkvb staged through an 8-slot smem ring via per-thread 4B cp.async, issued
// 6 steps ahead (covers DRAM latency). elu producer runs one step ahead into a
// 4-deep sq/sk buffer. One __syncthreads + one wait_group per step.
__global__ __launch_bounds__(512) void delta_kernel(const float* __restrict__ qkvb,
                                                    unsigned short* __restrict__ ohi,
                                                    unsigned short* __restrict__ olo) {
    const int tid = threadIdx.x;
    const int hl = tid >> 8;             // head within CTA (0/1)
    const int ht = tid & 255;
    const int lane = tid & 31;
    const int w8 = ht >> 5;              // warp within head (0..7)
    const int r = w8 * 8 + (lane & 7);   // W row (0..63)
    const int seg = lane >> 3;           // column segment (0..3)
    const int j0 = seg * 16;
    const int bh = blockIdx.x * 2 + hl;  // 0..255
    const int b = bh >> 3, h = bh & 7;

    __shared__ float ring[2][8][200];    // [head][slot][193 floats used]
    __shared__ float sq[2][4][64];       // [head][t mod 4][dim]
    __shared__ float sk[2][4][64];

    const float* base = qkvb + (size_t)b * NPROJ + h * 193;
    const size_t tstr = (size_t)BSZ * NPROJ;

    float W[16];
    #pragma unroll
    for (int i = 0; i < 16; i++) W[i] = 0.0f;

    // prologue: issue steps 0..5 into slots 0..5 (one commit group per step)
    if (ht < 193) {
        #pragma unroll
        for (int s = 0; s < 6; s++) {
            cp4(smem_u32(&ring[hl][s][ht]), base + (size_t)s * tstr + ht);
            cp_commit();
        }
        asm volatile("cp.async.wait_group 4;\n" ::: "memory");   // steps 0,1 complete
    }
    __syncthreads();

    // elu for step 0
    if (ht < 128) {
        float xv = ring[hl][0][ht];
        float y = (xv > 0.f) ? (xv + 1.0f) : __expf(xv);
        if (ht < 64) sq[hl][0][ht] = y;
        else         sk[hl][0][ht - 64] = y;
    }
    __syncthreads();

    for (int t = 0; t < SLEN; t++) {
        const int tb = t & 3;

        // phase 1: elu for step t+1 (ring slot (t+1)&7 guaranteed by prev wait+bar)
        if (ht < 128 && t + 1 < SLEN) {
            float xv = ring[hl][(t + 1) & 7][ht];
            float y = (xv > 0.f) ? (xv + 1.0f) : __expf(xv);
            if (ht < 64) sq[hl][(t + 1) & 3][ht] = y;
            else         sk[hl][(t + 1) & 3][ht - 64] = y;
        }

        // phase 2: issue step t+6 into slot (t+6)&7 (held step t-2, fully
        // consumed before the previous barrier); always commit to keep
        // per-thread group counting uniform.
        if (ht < 193) {
            if (t + 6 < SLEN)
                cp4(smem_u32(&ring[hl][(t + 6) & 7][ht]), base + (size_t)(t + 6) * tstr + ht);
            cp_commit();
            asm volatile("cp.async.wait_group 4;\n" ::: "memory");  // covers step t+2
        }
        __syncthreads();

        // phase 3: compute step t from smem only
        const float* rg = ring[hl][t & 7];
        float vt = rg[128 + r];
        float xb = rg[192];
        float bsig = 1.0f / (1.0f + __expf(-xb));

        float s1 = sq[hl][tb][lane] + sq[hl][tb][lane + 32];
        float s2 = sk[hl][tb][lane] + sk[hl][tb][lane + 32];
        #pragma unroll
        for (int o = 16; o > 0; o >>= 1) {
            s1 += __shfl_xor_sync(0xffffffffu, s1, o);
            s2 += __shfl_xor_sync(0xffffffffu, s2, o);
        }
        float rq = 1.0f / s1;
        float rk = 1.0f / s2;

        // partial dot W[r, j0:j0+16) . k
        float kreg[16];
        float pv0 = 0.f, pv1 = 0.f, pv2 = 0.f, pv3 = 0.f;
        #pragma unroll
        for (int j = 0; j < 4; j++) {
            float4 k4 = *(const float4*)&sk[hl][tb][j0 + j * 4];
            kreg[j*4+0] = k4.x; kreg[j*4+1] = k4.y; kreg[j*4+2] = k4.z; kreg[j*4+3] = k4.w;
            pv0 = fmaf(W[j*4+0], k4.x, pv0);
            pv1 = fmaf(W[j*4+1], k4.y, pv1);
            pv2 = fmaf(W[j*4+2], k4.z, pv2);
            pv3 = fmaf(W[j*4+3], k4.w, pv3);
        }
        float pv = (pv0 + pv1) + (pv2 + pv3);
        pv += __shfl_xor_sync(0xffffffffu, pv, 8);
        pv += __shfl_xor_sync(0xffffffffu, pv, 16);
        float upd = bsig * (vt - pv * rk) * rk;

        // W += upd*k ; po = W_new . q (partial)
        float po0 = 0.f, po1 = 0.f, po2 = 0.f, po3 = 0.f;
        #pragma unroll
        for (int j = 0; j < 4; j++) {
            float4 q4 = *(const float4*)&sq[hl][tb][j0 + j * 4];
            W[j*4+0] = fmaf(upd, kreg[j*4+0], W[j*4+0]);
            po0 = fmaf(W[j*4+0], q4.x, po0);
            W[j*4+1] = fmaf(upd, kreg[j*4+1], W[j*4+1]);
            po1 = fmaf(W[j*4+1], q4.y, po1);
            W[j*4+2] = fmaf(upd, kreg[j*4+2], W[j*4+2]);
            po2 = fmaf(W[j*4+2], q4.z, po2);
            W[j*4+3] = fmaf(upd, kreg[j*4+3], W[j*4+3]);
            po3 = fmaf(W[j*4+3], q4.w, po3);
        }
        float po = (po0 + po1) + (po2 + po3);
        po += __shfl_xor_sync(0xffffffffu, po, 8);
        po += __shfl_xor_sync(0xffffffffu, po, 16);
        float o = po * rq;

        if (seg == 0) {
            size_t oi = ((size_t)t * BSZ + b) * (size_t)INDIM + h * HD + r;
            __nv_bfloat16 oh = __float2bfloat16(o);
            __nv_bfloat16 ol = __float2bfloat16(o - __bfloat162float(oh));
            ohi[oi] = bf16_bits(oh);
            olo[oi] = bf16_bits(ol);
        }
    }
}

// ---------------- launch ----------------
extern "C" void kernel_launch(void* const* d_in, const int* in_sizes, int n_in,
                              void* d_out, int out_size) {
    const float* x      = (const float*)d_in[0];
    const float* gamma  = (const float*)d_in[1];
    const float* beta   = (const float*)d_in[2];
    const float* w_slow = (const float*)d_in[3];
    const float* w_out  = (const float*)d_in[4];
    float* out = (float*)d_out;

    float* qkvb;
    unsigned short *hhi, *hlo, *ohi, *olo, *wshi, *wslo, *wohi, *wolo;
    cudaGetSymbolAddress((void**)&qkvb, g_qkvb);
    cudaGetSymbolAddress((void**)&hhi, g_hhi);
    cudaGetSymbolAddress((void**)&hlo, g_hlo);
    cudaGetSymbolAddress((void**)&ohi, g_ohi);
    cudaGetSymbolAddress((void**)&olo, g_olo);
    cudaGetSymbolAddress((void**)&wshi, g_wshi);
    cudaGetSymbolAddress((void**)&wslo, g_wslo);
    cudaGetSymbolAddress((void**)&wohi, g_wohi);
    cudaGetSymbolAddress((void**)&wolo, g_wolo);

    // Idempotent, host-side, not stream-ordered: safe under graph capture.
    cudaFuncSetAttribute(gemm_split, cudaFuncAttributeMaxDynamicSharedMemorySize, SMEM_GEMM);

    ln_kernel<<<NTOK, 128>>>(x, gamma, beta, hhi, hlo);
    split_kernel<<<(INDIM * NPROJ + 255) / 256, 256>>>(w_slow, wshi, wslo, INDIM * NPROJ);
    split_kernel<<<(INDIM * INDIM + 255) / 256, 256>>>(w_out, wohi, wolo, INDIM * INDIM);

    dim3 g1((NPROJ + 127) / 128, NTOK / 128);
    gemm_split<<<g1, 256, SMEM_GEMM>>>((const __nv_bfloat16*)hhi, (const __nv_bfloat16*)hlo,
                                       (const __nv_bfloat16*)wshi, (const __nv_bfloat16*)wslo,
                                       nullptr, qkvb, NTOK, NPROJ, INDIM);

    delta_kernel<<<BSZ * NH / 2, 512>>>(qkvb, ohi, olo);

    dim3 g2(INDIM / 128, NTOK / 128);
    gemm_split<<<g2, 256, SMEM_GEMM>>>((const __nv_bfloat16*)ohi, (const __nv_bfloat16*)olo,
                                       (const __nv_bfloat16*)wohi, (const __nv_bfloat16*)wolo,
                                       x, out, NTOK, INDIM, NH * HD);
}